// round 4
// baseline (speedup 1.0000x reference)
#include <cuda_runtime.h>
#include <cstdint>
#include <cstddef>

// out[b,i,j] = W[words[b,i], words[b,j]]  (+ root[words[b,i]] when i==j)
// V=10000, B=8, N=2048
//
// R4: (1) single-CTA fused pre-pass (count/scan/compact/place) emitting a
// compact nonempty-row worklist; (2) warp-specialized persistent main kernel:
// 1 producer warp keeps a 5-deep TMA ring of 40KB W rows full (chunked atomic
// grabs), 16 consumer warps gather+store output rows.

#define V 10000
#define B_DIM 8
#define N_DIM 2048
#define NITEMS (B_DIM * N_DIM)     // 16384
#define ROW_BYTES (V * 4)          // 40000
#define NSLOTS 5
#define CONSUMERS 512
#define THREADS (CONSUMERS + 32)   // 16 consumer warps + 1 producer warp
#define GRID_MAIN 152              // 1 CTA per SM on GB300
#define CHUNK 8                    // rows grabbed per atomic

__device__ int d_rows[V];
__device__ int d_rbeg[V];
__device__ int d_rend[V];
__device__ int d_items[NITEMS];
__device__ int d_nrows;
__device__ int d_wcursor;

// ================= fused pre-pass (one CTA) =================
#define PRE_T 1024
#define BINS_PER_T 10              // 1024*10 = 10240 >= V

__global__ __launch_bounds__(PRE_T) void prepass_kernel(const int* __restrict__ words)
{
    __shared__ int cnt[V];         // counts -> later global cursors
    __shared__ int part[PRE_T];
    __shared__ int fpart[PRE_T];

    const int t = threadIdx.x;

    for (int i = t; i < V; i += PRE_T) cnt[i] = 0;
    __syncthreads();

    for (int k = t; k < NITEMS; k += PRE_T)
        atomicAdd(&cnt[__ldg(words + k)], 1);
    __syncthreads();

    // dual scan: item counts + nonempty flags
    const int base = t * BINS_PER_T;
    int loc[BINS_PER_T], floc[BINS_PER_T];
    int s = 0, f = 0;
    #pragma unroll
    for (int k = 0; k < BINS_PER_T; ++k) {
        int idx = base + k;
        loc[k] = s; floc[k] = f;
        int c = (idx < V) ? cnt[idx] : 0;
        s += c; f += (c > 0);
    }
    part[t] = s; fpart[t] = f;
    __syncthreads();
    for (int off = 1; off < PRE_T; off <<= 1) {
        int a = 0, b0 = 0;
        if (t >= off) { a = part[t - off]; b0 = fpart[t - off]; }
        __syncthreads();
        if (t >= off) { part[t] += a; fpart[t] += b0; }
        __syncthreads();
    }
    const int excl  = (t == 0) ? 0 : part[t - 1];
    const int fexcl = (t == 0) ? 0 : fpart[t - 1];

    #pragma unroll
    for (int k = 0; k < BINS_PER_T; ++k) {
        int idx = base + k;
        if (idx < V) {
            int c = cnt[idx];
            int off = excl + loc[k];
            if (c > 0) {
                int fi = fexcl + floc[k];
                d_rows[fi] = idx;
                d_rbeg[fi] = off;
                d_rend[fi] = off + c;
            }
        }
    }
    if (t == PRE_T - 1) {
        d_nrows = fpart[PRE_T - 1];
        d_wcursor = 0;
    }
    __syncthreads();
    // convert counts -> running cursors (global item offsets)
    #pragma unroll
    for (int k = 0; k < BINS_PER_T; ++k) {
        int idx = base + k;
        if (idx < V) cnt[idx] = excl + loc[k];
    }
    __syncthreads();

    for (int k = t; k < NITEMS; k += PRE_T) {
        int r = __ldg(words + k);
        int p = atomicAdd(&cnt[r], 1);
        d_items[p] = k;
    }
}

// ================= mbarrier / TMA helpers =================
__device__ __forceinline__ void mbar_init(uint32_t mbar, uint32_t count) {
    asm volatile("mbarrier.init.shared.b64 [%0], %1;" :: "r"(mbar), "r"(count) : "memory");
}
__device__ __forceinline__ void mbar_expect_tx(uint32_t mbar, uint32_t bytes) {
    asm volatile("mbarrier.arrive.expect_tx.shared.b64 _, [%0], %1;"
                 :: "r"(mbar), "r"(bytes) : "memory");
}
__device__ __forceinline__ void mbar_arrive(uint32_t mbar) {
    asm volatile("mbarrier.arrive.shared.b64 _, [%0];" :: "r"(mbar) : "memory");
}
__device__ __forceinline__ void bulk_copy_g2s(uint32_t dst_smem, const void* src,
                                              uint32_t bytes, uint32_t mbar) {
    asm volatile("cp.async.bulk.shared::cta.global.mbarrier::complete_tx::bytes "
                 "[%0], [%1], %2, [%3];"
                 :: "r"(dst_smem), "l"(src), "r"(bytes), "r"(mbar) : "memory");
}
__device__ __forceinline__ void mbar_wait(uint32_t mbar, uint32_t phase) {
    asm volatile(
        "{\n\t"
        ".reg .pred P;\n\t"
        "WAIT_%=:\n\t"
        "mbarrier.try_wait.parity.acquire.cta.shared::cta.b64 P, [%0], %1, 0x989680;\n\t"
        "@P bra DONE_%=;\n\t"
        "bra WAIT_%=;\n\t"
        "DONE_%=:\n\t"
        "}"
        :: "r"(mbar), "r"(phase) : "memory");
}

// ================= main kernel =================
__global__ __launch_bounds__(THREADS) void pair_gather_ws_kernel(
    const int* __restrict__ words,
    const float* __restrict__ W,
    const float* __restrict__ root,
    float* __restrict__ out)
{
    extern __shared__ float sbuf[];   // NSLOTS * V floats, then barriers
    __shared__ int s_mr[NSLOTS], s_mb[NSLOTS], s_me[NSLOTS];

    const int t = threadIdx.x;
    const uint32_t smem_base = (uint32_t)__cvta_generic_to_shared(sbuf);
    const uint32_t bar_base  = smem_base + NSLOTS * ROW_BYTES; // 16B-aligned
    // full[s] = bar_base + s*16, empty[s] = bar_base + s*16 + 8

    if (t == 0) {
        #pragma unroll
        for (int s0 = 0; s0 < NSLOTS; ++s0) {
            mbar_init(bar_base + s0 * 16, 1);       // full: producer arrive
            mbar_init(bar_base + s0 * 16 + 8, 1);   // empty: one consumer arrive
        }
    }
    __syncthreads();

    if (t >= CONSUMERS) {
        // ---------------- producer warp ----------------
        const int lane = t - CONSUMERS;
        if (lane == 0)
            asm volatile("fence.proxy.async.shared::cta;" ::: "memory");
        __syncwarp();

        const int nrows = d_nrows;
        int qpos = CHUNK;                 // force first fetch
        int myr = -1, myb = 0, mye = 0, basei = 0;

        for (int k = 0;; ++k) {
            const int slot = k % NSLOTS;
            const int n    = k / NSLOTS;
            // wait slot empty (parity starts at 1: first pass is free)
            if (lane == 0)
                mbar_wait(bar_base + slot * 16 + 8, (unsigned)((n & 1) ^ 1));
            __syncwarp();

            if (qpos == CHUNK) {
                if (lane == 0) basei = atomicAdd(&d_wcursor, CHUNK);
                basei = __shfl_sync(0xFFFFFFFF, basei, 0);
                const int idx = basei + lane;
                const bool v = (lane < CHUNK) && (idx < nrows);
                myr = v ? __ldg(d_rows + idx) : -1;
                myb = v ? __ldg(d_rbeg + idx) : 0;
                mye = v ? __ldg(d_rend + idx) : 0;
                qpos = 0;
            }
            const int r = __shfl_sync(0xFFFFFFFF, myr, qpos);
            const int b = __shfl_sync(0xFFFFFFFF, myb, qpos);
            const int e = __shfl_sync(0xFFFFFFFF, mye, qpos);
            ++qpos;

            if (lane == 0) {
                s_mr[slot] = r; s_mb[slot] = b; s_me[slot] = e;
                if (r >= 0) {
                    mbar_expect_tx(bar_base + slot * 16, ROW_BYTES);
                    bulk_copy_g2s(smem_base + slot * ROW_BYTES,
                                  W + (size_t)r * V, ROW_BYTES,
                                  bar_base + slot * 16);
                } else {
                    mbar_arrive(bar_base + slot * 16);   // sentinel
                }
            }
            if (r < 0) break;
        }
    } else {
        // ---------------- consumer warps ----------------
        for (int k = 0;; ++k) {
            const int slot = k % NSLOTS;
            const int n    = k / NSLOTS;
            mbar_wait(bar_base + slot * 16, (unsigned)(n & 1));

            const int r = s_mr[slot];
            if (r < 0) break;
            const int b = s_mb[slot];
            const int e = s_me[slot];
            const float rootv = __ldg(root + r);
            const float* __restrict__ row = sbuf + (size_t)slot * V;

            for (int it = b; it < e; ++it) {
                const int blk = __ldg(d_items + it);   // b*N + i
                const int bb  = blk >> 11;
                const int i   = blk & (N_DIM - 1);
                const int4 c  = __ldg(reinterpret_cast<const int4*>(
                                         words + (size_t)bb * N_DIM) + t);
                const int j0 = t * 4;
                float4 v;
                v.x = row[c.x];
                v.y = row[c.y];
                v.z = row[c.z];
                v.w = row[c.w];
                const unsigned d = (unsigned)(i - j0);
                if (d < 4u) {
                    if      (d == 0u) v.x += rootv;
                    else if (d == 1u) v.y += rootv;
                    else if (d == 2u) v.z += rootv;
                    else              v.w += rootv;
                }
                *reinterpret_cast<float4*>(out + (size_t)blk * N_DIM + j0) = v;
            }

            // all consumers done reading this slot -> release to producer
            asm volatile("bar.sync 1, %0;" :: "n"(CONSUMERS) : "memory");
            if (t == 0) mbar_arrive(bar_base + slot * 16 + 8);
        }
    }
}

// ================= launch =================
extern "C" void kernel_launch(void* const* d_in, const int* in_sizes, int n_in,
                              void* d_out, int out_size)
{
    const int*   words = (const int*)  d_in[0];
    const float* W     = (const float*)d_in[1];
    const float* root  = (const float*)d_in[2];
    float*       out   = (float*)d_out;

    static const size_t SMEM_DYN = (size_t)NSLOTS * ROW_BYTES + NSLOTS * 16;
    cudaFuncSetAttribute(pair_gather_ws_kernel,
                         cudaFuncAttributeMaxDynamicSharedMemorySize,
                         (int)SMEM_DYN);

    prepass_kernel<<<1, PRE_T>>>(words);
    pair_gather_ws_kernel<<<GRID_MAIN, THREADS, SMEM_DYN>>>(words, W, root, out);
}